// round 13
// baseline (speedup 1.0000x reference)
#include <cuda_runtime.h>
#include <cuda_bf16.h>
#include <math.h>
#include <stdint.h>

// Problem constants
#define N_ 30000
#define D_ 128
#define E_ 240000
#define E2_ (E_ + N_)          // 270000
#define L_ 6
#define NEG_SLOPE 0.2f
#define EPS_ 1e-5f

// -------------------- device scratch --------------------
__device__ float g_h[N_ * D_];
__device__ float g_xg[N_ * D_];
__device__ float g_xl[N_ * D_];
__device__ float g_xr[N_ * D_];
// packed weights, [mat][kpair w 0..63][n 0..127]: bf16x2 along k, hi + lo residual
__device__ uint32_t g_Wph[13 * 8192];
__device__ uint32_t g_Wpl[13 * 8192];

__device__ int    g_deg[N_];
__device__ int    g_cursor[N_];
__device__ int    g_rowptr[N_ + 1];
__device__ int    g_srcs[E2_];
__device__ int    g_scanbuf[30720];
__device__ int    g_bsum[32];

__device__ double g_lnred[12];
__device__ float  g_bnsum[D_];
__device__ float  g_bnsq[D_];

// -------------------- helpers --------------------
__device__ __forceinline__ void mma_bf16(float* d, const uint32_t* a, const uint32_t* b) {
    asm volatile(
        "mma.sync.aligned.m16n8k16.row.col.f32.bf16.bf16.f32 "
        "{%0,%1,%2,%3}, {%4,%5,%6,%7}, {%8,%9}, {%0,%1,%2,%3};"
        : "+f"(d[0]), "+f"(d[1]), "+f"(d[2]), "+f"(d[3])
        : "r"(a[0]), "r"(a[1]), "r"(a[2]), "r"(a[3]), "r"(b[0]), "r"(b[1]));
}
__device__ __forceinline__ void split2(float x, float y, uint32_t& hi, uint32_t& lo) {
    __nv_bfloat16 hx = __float2bfloat16(x), hy = __float2bfloat16(y);
    float lx = x - __bfloat162float(hx);
    float ly = y - __bfloat162float(hy);
    __nv_bfloat16 lxh = __float2bfloat16(lx), lyh = __float2bfloat16(ly);
    hi = (uint32_t)__bfloat16_as_ushort(hx) | ((uint32_t)__bfloat16_as_ushort(hy) << 16);
    lo = (uint32_t)__bfloat16_as_ushort(lxh) | ((uint32_t)__bfloat16_as_ushort(lyh) << 16);
}
__device__ __forceinline__ float2 bf2f(uint32_t u) {
    __nv_bfloat162 h = *reinterpret_cast<__nv_bfloat162*>(&u);
    return __bfloat1622float2(h);
}
__device__ __forceinline__ float leaky(float v) { return v > 0.f ? v : NEG_SLOPE * v; }

// -------------------- small kernels --------------------
__global__ void zero_kernel() {
    int i = blockIdx.x * blockDim.x + threadIdx.x;
    if (i < N_) { g_deg[i] = 0; g_cursor[i] = 0; }
    if (i < 12) g_lnred[i] = 0.0;
    if (i < D_) { g_bnsum[i] = 0.f; g_bnsq[i] = 0.f; }
}

__global__ void gather_kernel(const int* __restrict__ x, const float* __restrict__ emb) {
    int i = blockIdx.x * blockDim.x + threadIdx.x;
    if (i >= N_ * 32) return;
    int n = i >> 5, c4 = i & 31;
    ((float4*)g_h)[i] = ((const float4*)(emb + (size_t)x[n] * D_))[c4];
}

__global__ void hist_kernel(const int* __restrict__ ei) {
    int e = blockIdx.x * blockDim.x + threadIdx.x;
    if (e >= E2_) return;
    int d = (e < E_) ? ei[E_ + e] : (e - E_);
    atomicAdd(&g_deg[d], 1);
}

__global__ void scan1_kernel() {
    __shared__ int sh[1024];
    int t = threadIdx.x, i = blockIdx.x * 1024 + t;
    int v = (i < N_) ? g_deg[i] : 0;
    sh[t] = v;
    __syncthreads();
    for (int o = 1; o < 1024; o <<= 1) {
        int u = (t >= o) ? sh[t - o] : 0;
        __syncthreads();
        sh[t] += u;
        __syncthreads();
    }
    g_scanbuf[i] = sh[t];
    if (t == 1023) g_bsum[blockIdx.x] = sh[1023];
}
__global__ void scan2_kernel() {
    int t = threadIdx.x;
    int orig = (t < 30) ? g_bsum[t] : 0;
    int v = orig;
    for (int o = 1; o < 32; o <<= 1) {
        int u = __shfl_up_sync(0xffffffffu, v, o);
        if (t >= o) v += u;
    }
    if (t < 30) g_bsum[t] = v - orig;
}
__global__ void scan3_kernel() {
    int t = threadIdx.x, i = blockIdx.x * 1024 + t;
    if (i > N_) return;
    int v = (i < N_) ? g_deg[i] : 0;
    g_rowptr[i] = g_bsum[blockIdx.x] + g_scanbuf[i] - v;
}

__global__ void scatter_kernel(const int* __restrict__ ei) {
    int e = blockIdx.x * blockDim.x + threadIdx.x;
    if (e >= E2_) return;
    int s, d;
    if (e < E_) { s = ei[e]; d = ei[E_ + e]; }
    else        { s = e - E_; d = s; }
    int pos = g_rowptr[d] + atomicAdd(&g_cursor[d], 1);
    g_srcs[pos] = s;
}

// pack weights: W[k][n] fp32 -> [w][n] bf16x2 hi/lo (w = k/2), 13 matrices
__global__ void pack_kernel(const float* __restrict__ Wl, const float* __restrict__ Wr,
                            const float* __restrict__ linW) {
    int idx = blockIdx.x * 256 + threadIdx.x;
    if (idx >= 13 * 8192) return;
    int mat = idx / 8192;
    int rem = idx - mat * 8192;
    int w = rem >> 7;
    int n = rem & 127;
    const float* src = (mat < 6) ? (Wl + mat * 16384)
                     : (mat < 12) ? (Wr + (mat - 6) * 16384) : linW;
    float v0 = src[(2 * w) * D_ + n];
    float v1 = src[(2 * w + 1) * D_ + n];
    uint32_t hi, lo;
    split2(v0, v1, hi, lo);
    g_Wph[mat * 8192 + w * 128 + n] = hi;
    g_Wpl[mat * 8192 + w * 128 + n] = lo;
}

// ---------------- hybrid GEMM: tensor cols 0-95 (w0-3), FMA cols 96-127 ----
// PRE: 0 identity, 1 LN(graph)+ReLU, 2 A+resid.  NB: 1 or 2 weight matrices.
#define PW 68
#define TILEU (32 * PW)                 // 2176 uints per limb array
#define BFOFF (2 * TILEU)               // Bf starts here (word offset)
#define GSMEM ((2 * TILEU + 2 * 4096) * 4)   // 50176 B

template<int PRE, int NB>
__global__ __launch_bounds__(256, 2) void gat_gemm(
    const float* __restrict__ A, const float* __restrict__ resid,
    const uint32_t* __restrict__ WhA, const uint32_t* __restrict__ WlA,
    const uint32_t* __restrict__ WhB, const uint32_t* __restrict__ WlB,
    const float* __restrict__ WfA, const float* __restrict__ WfB,
    const float* __restrict__ biasA, const float* __restrict__ biasB,
    float* __restrict__ CA, float* __restrict__ CB,
    const float* __restrict__ lnG, const float* __restrict__ lnB, int lnslot)
{
    extern __shared__ uint32_t smu[];
    uint32_t* Ah = smu;
    uint32_t* Al = smu + TILEU;
    float* Bf    = (float*)(smu + BFOFF);   // [mat][k][32] fp32, cols 96..127

    const int tid = threadIdx.x, wid = tid >> 5, lane = tid & 31;
    const int row0 = blockIdx.x * 32;

    float mu = 0.f, inv = 0.f;
    if (PRE == 1) {
        double s  = g_lnred[lnslot * 2 + 0];
        double sq = g_lnred[lnslot * 2 + 1];
        const double cnt = (double)N_ * (double)D_;
        double m = s / cnt;
        mu  = (float)m;
        inv = (float)(1.0 / sqrt(sq / cnt - m * m + (double)EPS_));
    }

    // ---- stage A (pre-op + bf16 split): row = tid>>3, octant = tid&7 ----
    {
        const int r = tid >> 3, oct = tid & 7;
        const bool aok = (row0 + r) < N_;
        const float* Arow = A + (size_t)(row0 + r) * D_;
        const float* Rrow = (PRE == 2) ? (resid + (size_t)(row0 + r) * D_) : nullptr;
#pragma unroll
        for (int i = 0; i < 4; i++) {
            int c4 = oct * 4 + i;             // float4 index 0..31
            float4 v = make_float4(0.f, 0.f, 0.f, 0.f);
            if (aok) v = *(const float4*)(Arow + c4 * 4);
            if (PRE == 1) {
                float4 lg = *(const float4*)(lnG + c4 * 4);
                float4 lb = *(const float4*)(lnB + c4 * 4);
                v.x = fmaxf((v.x - mu) * inv * lg.x + lb.x, 0.f);
                v.y = fmaxf((v.y - mu) * inv * lg.y + lb.y, 0.f);
                v.z = fmaxf((v.z - mu) * inv * lg.z + lb.z, 0.f);
                v.w = fmaxf((v.w - mu) * inv * lg.w + lb.w, 0.f);
            } else if (PRE == 2) {
                if (aok) {
                    float4 rv = *(const float4*)(Rrow + c4 * 4);
                    v.x += rv.x; v.y += rv.y; v.z += rv.z; v.w += rv.w;
                }
            }
            uint32_t h0, l0, h1, l1;
            split2(v.x, v.y, h0, l0);
            split2(v.z, v.w, h1, l1);
            *(uint2*)&Ah[r * PW + c4 * 2] = make_uint2(h0, h1);
            *(uint2*)&Al[r * PW + c4 * 2] = make_uint2(l0, l1);
        }
        // ---- stage Bf (fp32 cols 96..127 for FMA warps) ----
#pragma unroll
        for (int i = 0; i < NB * 4; i++) {
            int idx = i * 256 + tid;          // over NB*1024 float4s
            int mat = idx >> 10, rem = idx & 1023;
            int k = rem >> 3, c4 = rem & 7;
            const float* Wf = (NB == 2 && mat) ? WfB : WfA;
            *(float4*)&Bf[mat * 4096 + k * 32 + c4 * 4] =
                *(const float4*)(Wf + (size_t)k * D_ + 96 + c4 * 4);
        }
    }
    __syncthreads();

    if (wid < 4) {
        // ============ tensor path: warp wid handles cols wid*24 .. +23 ======
        const int g  = lane >> 2;        // 0..7
        const int tg = lane & 3;         // 0..3
        const int wc = wid * 24;
        const int bbase = tg * 128 + wc + g;

        float acc0[2][3][4], acc1[2][3][4];
#pragma unroll
        for (int mi = 0; mi < 2; mi++)
#pragma unroll
            for (int ni = 0; ni < 3; ni++)
#pragma unroll
                for (int j = 0; j < 4; j++) {
                    acc0[mi][ni][j] = 0.f;
                    if (NB == 2) acc1[mi][ni][j] = 0.f;
                }

#pragma unroll 2
        for (int ks = 0; ks < 8; ks++) {
            const int k0 = ks * 8;
            uint32_t ah[2][4], al[2][4];
#pragma unroll
            for (int mi = 0; mi < 2; mi++) {
                int o1 = (mi * 16 + g) * PW + k0 + tg;
                int o2 = o1 + 8 * PW;
                ah[mi][0] = Ah[o1]; ah[mi][1] = Ah[o2];
                ah[mi][2] = Ah[o1 + 4]; ah[mi][3] = Ah[o2 + 4];
                al[mi][0] = Al[o1]; al[mi][1] = Al[o2];
                al[mi][2] = Al[o1 + 4]; al[mi][3] = Al[o2 + 4];
            }
            {
                uint32_t bh[3][2], bl[3][2];
                const int bo = k0 * 128 + bbase;
#pragma unroll
                for (int ni = 0; ni < 3; ni++) {
                    bh[ni][0] = WhA[bo + ni * 8];
                    bh[ni][1] = WhA[bo + 512 + ni * 8];
                    bl[ni][0] = WlA[bo + ni * 8];
                    bl[ni][1] = WlA[bo + 512 + ni * 8];
                }
#pragma unroll
                for (int mi = 0; mi < 2; mi++)
#pragma unroll
                    for (int ni = 0; ni < 3; ni++)
                        mma_bf16(acc0[mi][ni], ah[mi], bh[ni]);
#pragma unroll
                for (int mi = 0; mi < 2; mi++)
#pragma unroll
                    for (int ni = 0; ni < 3; ni++)
                        mma_bf16(acc0[mi][ni], ah[mi], bl[ni]);
#pragma unroll
                for (int mi = 0; mi < 2; mi++)
#pragma unroll
                    for (int ni = 0; ni < 3; ni++)
                        mma_bf16(acc0[mi][ni], al[mi], bh[ni]);
            }
            if (NB == 2) {
                uint32_t bh[3][2], bl[3][2];
                const int bo = k0 * 128 + bbase;
#pragma unroll
                for (int ni = 0; ni < 3; ni++) {
                    bh[ni][0] = WhB[bo + ni * 8];
                    bh[ni][1] = WhB[bo + 512 + ni * 8];
                    bl[ni][0] = WlB[bo + ni * 8];
                    bl[ni][1] = WlB[bo + 512 + ni * 8];
                }
#pragma unroll
                for (int mi = 0; mi < 2; mi++)
#pragma unroll
                    for (int ni = 0; ni < 3; ni++)
                        mma_bf16(acc1[mi][ni], ah[mi], bh[ni]);
#pragma unroll
                for (int mi = 0; mi < 2; mi++)
#pragma unroll
                    for (int ni = 0; ni < 3; ni++)
                        mma_bf16(acc1[mi][ni], ah[mi], bl[ni]);
#pragma unroll
                for (int mi = 0; mi < 2; mi++)
#pragma unroll
                    for (int ni = 0; ni < 3; ni++)
                        mma_bf16(acc1[mi][ni], al[mi], bh[ni]);
            }
        }

        // epilogue (tensor cols)
#pragma unroll
        for (int mat = 0; mat < NB; mat++) {
            const float* bias = mat ? biasB : biasA;
            float* C          = mat ? CB : CA;
#pragma unroll
            for (int mi = 0; mi < 2; mi++) {
                int r1 = row0 + mi * 16 + g;
                int r2 = r1 + 8;
#pragma unroll
                for (int ni = 0; ni < 3; ni++) {
                    float* a = mat ? acc1[mi][ni] : acc0[mi][ni];
                    int col = wc + ni * 8 + tg * 2;
                    float2 bv = *(const float2*)(bias + col);
                    if (r1 < N_) {
                        float2 o = make_float2(a[0] + bv.x, a[1] + bv.y);
                        *(float2*)(C + (size_t)r1 * D_ + col) = o;
                    }
                    if (r2 < N_) {
                        float2 o = make_float2(a[2] + bv.x, a[3] + bv.y);
                        *(float2*)(C + (size_t)r2 * D_ + col) = o;
                    }
                }
            }
        }
    } else {
        // ============ FMA path: warp wid handles cols 96+(wid-4)*8 .. +7 ====
        const int off = (wid - 4) * 8;       // 0,8,16,24 within the 32-col group
        const uint32_t* AhRow = Ah + lane * PW;
        const uint32_t* AlRow = Al + lane * PW;

        float accA[8], accB[8];
#pragma unroll
        for (int j = 0; j < 8; j++) { accA[j] = 0.f; accB[j] = 0.f; }

#pragma unroll 4
        for (int w = 0; w < 64; w++) {
            float2 fh = bf2f(AhRow[w]);
            float2 fl = bf2f(AlRow[w]);
            float a0 = fh.x + fl.x;              // k = 2w
            float a1 = fh.y + fl.y;              // k = 2w+1
            {
                const float* B = Bf + (2 * w) * 32 + off;
                float4 b00 = *(const float4*)B;
                float4 b01 = *(const float4*)(B + 4);
                float4 b10 = *(const float4*)(B + 32);
                float4 b11 = *(const float4*)(B + 36);
                accA[0] = fmaf(a0, b00.x, accA[0]); accA[1] = fmaf(a0, b00.y, accA[1]);
                accA[2] = fmaf(a0, b00.z, accA[2]); accA[3] = fmaf(a0, b00.w, accA[3]);
                accA[4] = fmaf(a0, b01.x, accA[4]); accA[5] = fmaf(a0, b01.y, accA[5]);
                accA[6] = fmaf(a0, b01.z, accA[6]); accA[7] = fmaf(a0, b01.w, accA[7]);
                accA[0] = fmaf(a1, b10.x, accA[0]); accA[1] = fmaf(a1, b10.y, accA[1]);
                accA[2] = fmaf(a1, b10.z, accA[2]); accA[3] = fmaf(a1, b10.w, accA[3]);
                accA[4] = fmaf(a1, b11.x, accA[4]); accA[5] = fmaf(a1, b11.y, accA[5]);
                accA[6] = fmaf(a1, b11.z, accA[6]); accA[7] = fmaf(a1, b11.w, accA[7]);
            }
            if (NB == 2) {
                const float* B = Bf + 4096 + (2 * w) * 32 + off;
                float4 b00 = *(const float4*)B;
                float4 b01 = *(const float4*)(B + 4);
                float4 b10 = *(const float4*)(B + 32);
                float4 b11 = *(const float4*)(B + 36);
                accB[0] = fmaf(a0, b00.x, accB[0]); accB[1] = fmaf(a0, b00.y, accB[1]);
                accB[2] = fmaf(a0, b00.z, accB[2]); accB[3] = fmaf(a0, b00.w, accB[3]);
                accB[4] = fmaf(a0, b01.x, accB[4]); accB[5] = fmaf(a0, b01.y, accB[5]);
                accB[6] = fmaf(a0, b01.z, accB[6]); accB[7] = fmaf(a0, b01.w, accB[7]);
                accB[0] = fmaf(a1, b10.x, accB[0]); accB[1] = fmaf(a1, b10.y, accB[1]);
                accB[2] = fmaf(a1, b10.z, accB[2]); accB[3] = fmaf(a1, b10.w, accB[3]);
                accB[4] = fmaf(a1, b11.x, accB[4]); accB[5] = fmaf(a1, b11.y, accB[5]);
                accB[6] = fmaf(a1, b11.z, accB[6]); accB[7] = fmaf(a1, b11.w, accB[7]);
            }
        }

        // epilogue (FMA cols): lane == row within tile
        int row = row0 + lane;
        if (row < N_) {
            int col = 96 + off;
            {
                float4 bv0 = *(const float4*)(biasA + col);
                float4 bv1 = *(const float4*)(biasA + col + 4);
                float4 o0 = make_float4(accA[0] + bv0.x, accA[1] + bv0.y,
                                        accA[2] + bv0.z, accA[3] + bv0.w);
                float4 o1 = make_float4(accA[4] + bv1.x, accA[5] + bv1.y,
                                        accA[6] + bv1.z, accA[7] + bv1.w);
                *(float4*)(CA + (size_t)row * D_ + col)     = o0;
                *(float4*)(CA + (size_t)row * D_ + col + 4) = o1;
            }
            if (NB == 2) {
                float4 bv0 = *(const float4*)(biasB + col);
                float4 bv1 = *(const float4*)(biasB + col + 4);
                float4 o0 = make_float4(accB[0] + bv0.x, accB[1] + bv0.y,
                                        accB[2] + bv0.z, accB[3] + bv0.w);
                float4 o1 = make_float4(accB[4] + bv1.x, accB[5] + bv1.y,
                                        accB[6] + bv1.z, accB[7] + bv1.w);
                *(float4*)(CB + (size_t)row * D_ + col)     = o0;
                *(float4*)(CB + (size_t)row * D_ + col + 4) = o1;
            }
        }
    }
}

// -------------------- aggregation (warp per dst) + fused LN stats ----------
template<int STATS>
__global__ __launch_bounds__(256) void agg_kernel(
    const float* __restrict__ att, const float* __restrict__ cbias, int slot)
{
    __shared__ float ssum[8], ssq[8];
    int tid = threadIdx.x;
    int warp = (blockIdx.x * blockDim.x + tid) >> 5;
    int lane = tid & 31;
    int wid = tid >> 5;

    float4 o = make_float4(0.f, 0.f, 0.f, 0.f);
    if (warp < N_) {
        const float4 attv = ((const float4*)att)[lane];
        const float4 xrv  = ((const float4*)(g_xr + (size_t)warp * D_))[lane];
        int beg = g_rowptr[warp], end = g_rowptr[warp + 1];

        float m = -INFINITY, lsum = 0.f;
        float4 acc = make_float4(0.f, 0.f, 0.f, 0.f);
        for (int e = beg; e < end; e++) {
            int s = g_srcs[e];
            float4 v = ((const float4*)(g_xl + (size_t)s * D_))[lane];
            float p = leaky(v.x + xrv.x) * attv.x
                    + leaky(v.y + xrv.y) * attv.y
                    + leaky(v.z + xrv.z) * attv.z
                    + leaky(v.w + xrv.w) * attv.w;
#pragma unroll
            for (int of = 16; of > 0; of >>= 1)
                p += __shfl_xor_sync(0xffffffffu, p, of);
            float mn    = fmaxf(m, p);
            float scale = __expf(m - mn);
            float w     = __expf(p - mn);
            acc.x = acc.x * scale + w * v.x;
            acc.y = acc.y * scale + w * v.y;
            acc.z = acc.z * scale + w * v.z;
            acc.w = acc.w * scale + w * v.w;
            lsum  = lsum * scale + w;
            m = mn;
        }
        float invl = 1.f / lsum;
        float4 cb = ((const float4*)cbias)[lane];
        o = make_float4(acc.x * invl + cb.x, acc.y * invl + cb.y,
                        acc.z * invl + cb.z, acc.w * invl + cb.w);
        ((float4*)(g_xg + (size_t)warp * D_))[lane] = o;
    }

    if (STATS) {
        float s = o.x + o.y + o.z + o.w;
        float q = o.x * o.x + o.y * o.y + o.z * o.z + o.w * o.w;
#pragma unroll
        for (int of = 16; of > 0; of >>= 1) {
            s += __shfl_xor_sync(0xffffffffu, s, of);
            q += __shfl_xor_sync(0xffffffffu, q, of);
        }
        if (lane == 0) { ssum[wid] = s; ssq[wid] = q; }
        __syncthreads();
        if (tid == 0) {
            double S = 0.0, Q = 0.0;
#pragma unroll
            for (int i = 0; i < 8; i++) { S += (double)ssum[i]; Q += (double)ssq[i]; }
            atomicAdd(&g_lnred[slot * 2 + 0], S);
            atomicAdd(&g_lnred[slot * 2 + 1], Q);
        }
    }
}

// -------------------- BatchNorm --------------------
__global__ void bnstats_kernel(const float* __restrict__ out) {
    int c = threadIdx.x;
    float s = 0.f, q = 0.f;
    for (int r = blockIdx.x; r < N_; r += gridDim.x) {
        float v = out[(size_t)r * D_ + c];
        s += v; q += v * v;
    }
    atomicAdd(&g_bnsum[c], s);
    atomicAdd(&g_bnsq[c], q);
}

__global__ void bnnorm_kernel(float* __restrict__ out,
                              const float* __restrict__ bng,
                              const float* __restrict__ bnb) {
    int i = blockIdx.x * blockDim.x + threadIdx.x;
    if (i >= N_ * 32) return;
    int c4 = i & 31;
    float4 v  = ((float4*)out)[i];
    float4 su = ((const float4*)g_bnsum)[c4];
    float4 qu = ((const float4*)g_bnsq)[c4];
    float4 g  = ((const float4*)bng)[c4];
    float4 b  = ((const float4*)bnb)[c4];
    const float invN = 1.f / (float)N_;
    float mu, var;
    mu = su.x * invN; var = qu.x * invN - mu * mu;
    v.x = (v.x - mu) * rsqrtf(var + EPS_) * g.x + b.x;
    mu = su.y * invN; var = qu.y * invN - mu * mu;
    v.y = (v.y - mu) * rsqrtf(var + EPS_) * g.y + b.y;
    mu = su.z * invN; var = qu.z * invN - mu * mu;
    v.z = (v.z - mu) * rsqrtf(var + EPS_) * g.z + b.z;
    mu = su.w * invN; var = qu.w * invN - mu * mu;
    v.w = (v.w - mu) * rsqrtf(var + EPS_) * g.w + b.w;
    ((float4*)out)[i] = v;
}

// -------------------- launch --------------------
extern "C" void kernel_launch(void* const* d_in, const int* in_sizes, int n_in,
                              void* d_out, int out_size) {
    const int*   x    = (const int*)d_in[0];
    const int*   ei   = (const int*)d_in[1];
    const float* emb  = (const float*)d_in[2];
    const float* Wl   = (const float*)d_in[3];
    const float* bl   = (const float*)d_in[4];
    const float* Wr   = (const float*)d_in[5];
    const float* br   = (const float*)d_in[6];
    const float* att  = (const float*)d_in[7];
    const float* cb   = (const float*)d_in[8];
    const float* lng  = (const float*)d_in[9];
    const float* lnb  = (const float*)d_in[10];
    const float* linW = (const float*)d_in[11];
    const float* linb = (const float*)d_in[12];
    const float* bng  = (const float*)d_in[13];
    const float* bnb  = (const float*)d_in[14];
    float* out = (float*)d_out;

    float *p_h, *p_xg, *p_xl, *p_xr;
    uint32_t *p_Wph, *p_Wpl;
    cudaGetSymbolAddress((void**)&p_h,  g_h);
    cudaGetSymbolAddress((void**)&p_xg, g_xg);
    cudaGetSymbolAddress((void**)&p_xl, g_xl);
    cudaGetSymbolAddress((void**)&p_xr, g_xr);
    cudaGetSymbolAddress((void**)&p_Wph, g_Wph);
    cudaGetSymbolAddress((void**)&p_Wpl, g_Wpl);

    cudaFuncSetAttribute(gat_gemm<0,2>, cudaFuncAttributeMaxDynamicSharedMemorySize, GSMEM);
    cudaFuncSetAttribute(gat_gemm<1,2>, cudaFuncAttributeMaxDynamicSharedMemorySize, GSMEM);
    cudaFuncSetAttribute(gat_gemm<2,1>, cudaFuncAttributeMaxDynamicSharedMemorySize, GSMEM);

    const int TPB = 256;
    zero_kernel<<<(N_ + TPB - 1) / TPB, TPB>>>();
    gather_kernel<<<(N_ * 32 + TPB - 1) / TPB, TPB>>>(x, emb);
    hist_kernel<<<(E2_ + TPB - 1) / TPB, TPB>>>(ei);
    scan1_kernel<<<30, 1024>>>();
    scan2_kernel<<<1, 32>>>();
    scan3_kernel<<<30, 1024>>>();
    scatter_kernel<<<(E2_ + TPB - 1) / TPB, TPB>>>(ei);
    pack_kernel<<<(13 * 8192 + 255) / 256, 256>>>(Wl, Wr, linW);

    const int GEMM_GRID = (N_ + 31) / 32;            // 938
    const int AGG_GRID  = (N_ * 32 + TPB - 1) / TPB; // warp per node

    for (int i = 0; i < L_; i++) {
        const float* Ain = (i == 0) ? p_h : p_xg;
        const uint32_t* WhL = p_Wph + (size_t)i * 8192;
        const uint32_t* WlL = p_Wpl + (size_t)i * 8192;
        const uint32_t* WhR = p_Wph + (size_t)(6 + i) * 8192;
        const uint32_t* WlR = p_Wpl + (size_t)(6 + i) * 8192;
        const float* WfL = Wl + (size_t)i * 16384;
        const float* WfR = Wr + (size_t)i * 16384;
        if (i == 0) {
            gat_gemm<0,2><<<GEMM_GRID, 256, GSMEM>>>(
                Ain, nullptr, WhL, WlL, WhR, WlR, WfL, WfR,
                bl + i * D_, br + i * D_, p_xl, p_xr, nullptr, nullptr, 0);
        } else {
            gat_gemm<1,2><<<GEMM_GRID, 256, GSMEM>>>(
                Ain, nullptr, WhL, WlL, WhR, WlR, WfL, WfR,
                bl + i * D_, br + i * D_, p_xl, p_xr,
                lng + (i - 1) * D_, lnb + (i - 1) * D_, i - 1);
        }
        if (i < L_ - 1)
            agg_kernel<1><<<AGG_GRID, 256>>>(att + i * D_, cb + i * D_, i);
        else
            agg_kernel<0><<<AGG_GRID, 256>>>(att + i * D_, cb + i * D_, 0);
    }

    gat_gemm<2,1><<<GEMM_GRID, 256, GSMEM>>>(
        p_xg, p_h, p_Wph + (size_t)12 * 8192, p_Wpl + (size_t)12 * 8192,
        nullptr, nullptr, linW, nullptr,
        linb, nullptr, out, nullptr, nullptr, nullptr, 0);
    bnstats_kernel<<<256, D_>>>(out);
    bnnorm_kernel<<<(N_ * 32 + TPB - 1) / TPB, TPB>>>(out, bng, bnb);
}

// round 16
// speedup vs baseline: 1.1735x; 1.1735x over previous
#include <cuda_runtime.h>
#include <cuda_bf16.h>
#include <math.h>
#include <stdint.h>

// Problem constants
#define N_ 30000
#define D_ 128
#define E_ 240000
#define E2_ (E_ + N_)          // 270000
#define L_ 6
#define NEG_SLOPE 0.2f
#define EPS_ 1e-5f

// -------------------- device scratch --------------------
__device__ float g_h[N_ * D_];
__device__ float g_xg[N_ * D_];
__device__ float g_xl[N_ * D_];
__device__ float g_xr[N_ * D_];
// packed weights, [mat][kpair w 0..63][n 0..127]: bf16x2 along k, hi + lo residual
__device__ uint32_t g_Wph[13 * 8192];
__device__ uint32_t g_Wpl[13 * 8192];

__device__ int    g_deg[N_];
__device__ int    g_cursor[N_];
__device__ int    g_rowptr[N_ + 1];
__device__ int    g_srcs[E2_];
__device__ int    g_scanbuf[30720];
__device__ int    g_bsum[32];

__device__ double g_lnred[12];
__device__ float  g_bnsum[D_];
__device__ float  g_bnsq[D_];

// -------------------- helpers --------------------
__device__ __forceinline__ void mma_bf16(float* d, const uint32_t* a, const uint32_t* b) {
    asm volatile(
        "mma.sync.aligned.m16n8k16.row.col.f32.bf16.bf16.f32 "
        "{%0,%1,%2,%3}, {%4,%5,%6,%7}, {%8,%9}, {%0,%1,%2,%3};"
        : "+f"(d[0]), "+f"(d[1]), "+f"(d[2]), "+f"(d[3])
        : "r"(a[0]), "r"(a[1]), "r"(a[2]), "r"(a[3]), "r"(b[0]), "r"(b[1]));
}
__device__ __forceinline__ void split2(float x, float y, uint32_t& hi, uint32_t& lo) {
    __nv_bfloat16 hx = __float2bfloat16(x), hy = __float2bfloat16(y);
    float lx = x - __bfloat162float(hx);
    float ly = y - __bfloat162float(hy);
    __nv_bfloat16 lxh = __float2bfloat16(lx), lyh = __float2bfloat16(ly);
    hi = (uint32_t)__bfloat16_as_ushort(hx) | ((uint32_t)__bfloat16_as_ushort(hy) << 16);
    lo = (uint32_t)__bfloat16_as_ushort(lxh) | ((uint32_t)__bfloat16_as_ushort(lyh) << 16);
}
__device__ __forceinline__ float leaky(float v) { return v > 0.f ? v : NEG_SLOPE * v; }

// -------------------- small kernels --------------------
__global__ void zero_kernel() {
    int i = blockIdx.x * blockDim.x + threadIdx.x;
    if (i < N_) { g_deg[i] = 0; g_cursor[i] = 0; }
    if (i < 12) g_lnred[i] = 0.0;
    if (i < D_) { g_bnsum[i] = 0.f; g_bnsq[i] = 0.f; }
}

__global__ void gather_kernel(const int* __restrict__ x, const float* __restrict__ emb) {
    int i = blockIdx.x * blockDim.x + threadIdx.x;
    if (i >= N_ * 32) return;
    int n = i >> 5, c4 = i & 31;
    ((float4*)g_h)[i] = ((const float4*)(emb + (size_t)x[n] * D_))[c4];
}

__global__ void hist_kernel(const int* __restrict__ ei) {
    int e = blockIdx.x * blockDim.x + threadIdx.x;
    if (e >= E2_) return;
    int d = (e < E_) ? ei[E_ + e] : (e - E_);
    atomicAdd(&g_deg[d], 1);
}

__global__ void scan1_kernel() {
    __shared__ int sh[1024];
    int t = threadIdx.x, i = blockIdx.x * 1024 + t;
    int v = (i < N_) ? g_deg[i] : 0;
    sh[t] = v;
    __syncthreads();
    for (int o = 1; o < 1024; o <<= 1) {
        int u = (t >= o) ? sh[t - o] : 0;
        __syncthreads();
        sh[t] += u;
        __syncthreads();
    }
    g_scanbuf[i] = sh[t];
    if (t == 1023) g_bsum[blockIdx.x] = sh[1023];
}
__global__ void scan2_kernel() {
    int t = threadIdx.x;
    int orig = (t < 30) ? g_bsum[t] : 0;
    int v = orig;
    for (int o = 1; o < 32; o <<= 1) {
        int u = __shfl_up_sync(0xffffffffu, v, o);
        if (t >= o) v += u;
    }
    if (t < 30) g_bsum[t] = v - orig;
}
__global__ void scan3_kernel() {
    int t = threadIdx.x, i = blockIdx.x * 1024 + t;
    if (i > N_) return;
    int v = (i < N_) ? g_deg[i] : 0;
    g_rowptr[i] = g_bsum[blockIdx.x] + g_scanbuf[i] - v;
}

__global__ void scatter_kernel(const int* __restrict__ ei) {
    int e = blockIdx.x * blockDim.x + threadIdx.x;
    if (e >= E2_) return;
    int s, d;
    if (e < E_) { s = ei[e]; d = ei[E_ + e]; }
    else        { s = e - E_; d = s; }
    int pos = g_rowptr[d] + atomicAdd(&g_cursor[d], 1);
    g_srcs[pos] = s;
}

// pack weights: W[k][n] fp32 -> [w][n] bf16x2 hi/lo (w = k/2), 13 matrices
__global__ void pack_kernel(const float* __restrict__ Wl, const float* __restrict__ Wr,
                            const float* __restrict__ linW) {
    int idx = blockIdx.x * 256 + threadIdx.x;
    if (idx >= 13 * 8192) return;
    int mat = idx / 8192;
    int rem = idx - mat * 8192;
    int w = rem >> 7;
    int n = rem & 127;
    const float* src = (mat < 6) ? (Wl + mat * 16384)
                     : (mat < 12) ? (Wr + (mat - 6) * 16384) : linW;
    float v0 = src[(2 * w) * D_ + n];
    float v1 = src[(2 * w + 1) * D_ + n];
    uint32_t hi, lo;
    split2(v0, v1, hi, lo);
    g_Wph[mat * 8192 + w * 128 + n] = hi;
    g_Wpl[mat * 8192 + w * 128 + n] = lo;
}

// -------------------- bf16-split mma.sync GEMM, M=32 tiles, B via L1 --------
// PRE: 0 identity, 1 LN(graph)+ReLU, 2 A+resid.  NB: 1 or 2 weight matrices.
#define PW 68
#define TILEU (32 * PW)             // 2176 uints per limb array
#define GSMEM (2 * TILEU * 4)       // 17408 B (A hi + lo)

template<int PRE, int NB>
__global__ __launch_bounds__(256, 3) void gat_gemm(
    const float* __restrict__ A, const float* __restrict__ resid,
    const uint32_t* __restrict__ WhA, const uint32_t* __restrict__ WlA,
    const uint32_t* __restrict__ WhB, const uint32_t* __restrict__ WlB,
    const float* __restrict__ biasA, const float* __restrict__ biasB,
    float* __restrict__ CA, float* __restrict__ CB,
    const float* __restrict__ lnG, const float* __restrict__ lnB, int lnslot)
{
    extern __shared__ uint32_t smu[];
    uint32_t* Ah = smu;
    uint32_t* Al = smu + TILEU;

    const int tid = threadIdx.x, wid = tid >> 5, lane = tid & 31;
    const int row0 = blockIdx.x * 32;

    float mu = 0.f, inv = 0.f;
    if (PRE == 1) {
        double s  = g_lnred[lnslot * 2 + 0];
        double sq = g_lnred[lnslot * 2 + 1];
        const double cnt = (double)N_ * (double)D_;
        double m = s / cnt;
        mu  = (float)m;
        inv = (float)(1.0 / sqrt(sq / cnt - m * m + (double)EPS_));
    }

    // ---- stage A (pre-op + bf16 split): row = tid>>3, octant = tid&7 ----
    {
        const int r = tid >> 3, oct = tid & 7;
        const bool aok = (row0 + r) < N_;
        const float* Arow = A + (size_t)(row0 + r) * D_;
        const float* Rrow = (PRE == 2) ? (resid + (size_t)(row0 + r) * D_) : nullptr;
#pragma unroll
        for (int i = 0; i < 4; i++) {
            int c4 = oct * 4 + i;             // float4 index 0..31
            float4 v = make_float4(0.f, 0.f, 0.f, 0.f);
            if (aok) v = *(const float4*)(Arow + c4 * 4);
            if (PRE == 1) {
                float4 lg = *(const float4*)(lnG + c4 * 4);
                float4 lb = *(const float4*)(lnB + c4 * 4);
                v.x = fmaxf((v.x - mu) * inv * lg.x + lb.x, 0.f);
                v.y = fmaxf((v.y - mu) * inv * lg.y + lb.y, 0.f);
                v.z = fmaxf((v.z - mu) * inv * lg.z + lb.z, 0.f);
                v.w = fmaxf((v.w - mu) * inv * lg.w + lb.w, 0.f);
            } else if (PRE == 2) {
                if (aok) {
                    float4 rv = *(const float4*)(Rrow + c4 * 4);
                    v.x += rv.x; v.y += rv.y; v.z += rv.z; v.w += rv.w;
                }
            }
            uint32_t h0, l0, h1, l1;
            split2(v.x, v.y, h0, l0);
            split2(v.z, v.w, h1, l1);
            *(uint2*)&Ah[r * PW + c4 * 2] = make_uint2(h0, h1);
            *(uint2*)&Al[r * PW + c4 * 2] = make_uint2(l0, l1);
        }
    }
    __syncthreads();

    const int g  = lane >> 2;        // 0..7
    const int tg = lane & 3;         // 0..3
    const int wc = wid * 16;         // warp col slab (16 cols per warp)

    float acc0[2][2][4], acc1[2][2][4];
#pragma unroll
    for (int mi = 0; mi < 2; mi++)
#pragma unroll
        for (int ni = 0; ni < 2; ni++)
#pragma unroll
            for (int j = 0; j < 4; j++) {
                acc0[mi][ni][j] = 0.f;
                if (NB == 2) acc1[mi][ni][j] = 0.f;
            }

    // B base offset into [w][n] arrays for this lane
    const int bbase = tg * 128 + wc + g;

#pragma unroll 2
    for (int ks = 0; ks < 8; ks++) {
        const int k0 = ks * 8;
        uint32_t ah[2][4], al[2][4];
#pragma unroll
        for (int mi = 0; mi < 2; mi++) {
            int o1 = (mi * 16 + g) * PW + k0 + tg;
            int o2 = o1 + 8 * PW;
            ah[mi][0] = Ah[o1]; ah[mi][1] = Ah[o2];
            ah[mi][2] = Ah[o1 + 4]; ah[mi][3] = Ah[o2 + 4];
            al[mi][0] = Al[o1]; al[mi][1] = Al[o2];
            al[mi][2] = Al[o1 + 4]; al[mi][3] = Al[o2 + 4];
        }
        {
            uint32_t bh[2][2], bl[2][2];
            const int bo = k0 * 128 + bbase;
#pragma unroll
            for (int ni = 0; ni < 2; ni++) {
                bh[ni][0] = WhA[bo + ni * 8];
                bh[ni][1] = WhA[bo + 512 + ni * 8];
                bl[ni][0] = WlA[bo + ni * 8];
                bl[ni][1] = WlA[bo + 512 + ni * 8];
            }
#pragma unroll
            for (int mi = 0; mi < 2; mi++)
#pragma unroll
                for (int ni = 0; ni < 2; ni++)
                    mma_bf16(acc0[mi][ni], ah[mi], bh[ni]);
#pragma unroll
            for (int mi = 0; mi < 2; mi++)
#pragma unroll
                for (int ni = 0; ni < 2; ni++)
                    mma_bf16(acc0[mi][ni], ah[mi], bl[ni]);
#pragma unroll
            for (int mi = 0; mi < 2; mi++)
#pragma unroll
                for (int ni = 0; ni < 2; ni++)
                    mma_bf16(acc0[mi][ni], al[mi], bh[ni]);
        }
        if (NB == 2) {
            uint32_t bh[2][2], bl[2][2];
            const int bo = k0 * 128 + bbase;
#pragma unroll
            for (int ni = 0; ni < 2; ni++) {
                bh[ni][0] = WhB[bo + ni * 8];
                bh[ni][1] = WhB[bo + 512 + ni * 8];
                bl[ni][0] = WlB[bo + ni * 8];
                bl[ni][1] = WlB[bo + 512 + ni * 8];
            }
#pragma unroll
            for (int mi = 0; mi < 2; mi++)
#pragma unroll
                for (int ni = 0; ni < 2; ni++)
                    mma_bf16(acc1[mi][ni], ah[mi], bh[ni]);
#pragma unroll
            for (int mi = 0; mi < 2; mi++)
#pragma unroll
                for (int ni = 0; ni < 2; ni++)
                    mma_bf16(acc1[mi][ni], ah[mi], bl[ni]);
#pragma unroll
            for (int mi = 0; mi < 2; mi++)
#pragma unroll
                for (int ni = 0; ni < 2; ni++)
                    mma_bf16(acc1[mi][ni], al[mi], bh[ni]);
        }
    }

    // ---- epilogue ----
#pragma unroll
    for (int mat = 0; mat < NB; mat++) {
        const float* bias = mat ? biasB : biasA;
        float* C          = mat ? CB : CA;
#pragma unroll
        for (int mi = 0; mi < 2; mi++) {
            int r1 = row0 + mi * 16 + g;
            int r2 = r1 + 8;
#pragma unroll
            for (int ni = 0; ni < 2; ni++) {
                float* a = mat ? acc1[mi][ni] : acc0[mi][ni];
                int col = wc + ni * 8 + tg * 2;
                float2 bv = *(const float2*)(bias + col);
                if (r1 < N_) {
                    float2 o = make_float2(a[0] + bv.x, a[1] + bv.y);
                    *(float2*)(C + (size_t)r1 * D_ + col) = o;
                }
                if (r2 < N_) {
                    float2 o = make_float2(a[2] + bv.x, a[3] + bv.y);
                    *(float2*)(C + (size_t)r2 * D_ + col) = o;
                }
            }
        }
    }
}

// -------------------- aggregation (warp per dst) + fused LN stats ----------
template<int STATS>
__global__ __launch_bounds__(256) void agg_kernel(
    const float* __restrict__ att, const float* __restrict__ cbias, int slot)
{
    __shared__ float ssum[8], ssq[8];
    int tid = threadIdx.x;
    int warp = (blockIdx.x * blockDim.x + tid) >> 5;
    int lane = tid & 31;
    int wid = tid >> 5;

    float4 o = make_float4(0.f, 0.f, 0.f, 0.f);
    if (warp < N_) {
        const float4 attv = ((const float4*)att)[lane];
        const float4 xrv  = ((const float4*)(g_xr + (size_t)warp * D_))[lane];
        int beg = g_rowptr[warp], end = g_rowptr[warp + 1];

        float m = -INFINITY, lsum = 0.f;
        float4 acc = make_float4(0.f, 0.f, 0.f, 0.f);
        for (int e = beg; e < end; e++) {
            int s = g_srcs[e];
            float4 v = ((const float4*)(g_xl + (size_t)s * D_))[lane];
            float p = leaky(v.x + xrv.x) * attv.x
                    + leaky(v.y + xrv.y) * attv.y
                    + leaky(v.z + xrv.z) * attv.z
                    + leaky(v.w + xrv.w) * attv.w;
#pragma unroll
            for (int of = 16; of > 0; of >>= 1)
                p += __shfl_xor_sync(0xffffffffu, p, of);
            float mn    = fmaxf(m, p);
            float scale = __expf(m - mn);
            float w     = __expf(p - mn);
            acc.x = acc.x * scale + w * v.x;
            acc.y = acc.y * scale + w * v.y;
            acc.z = acc.z * scale + w * v.z;
            acc.w = acc.w * scale + w * v.w;
            lsum  = lsum * scale + w;
            m = mn;
        }
        float invl = 1.f / lsum;
        float4 cb = ((const float4*)cbias)[lane];
        o = make_float4(acc.x * invl + cb.x, acc.y * invl + cb.y,
                        acc.z * invl + cb.z, acc.w * invl + cb.w);
        ((float4*)(g_xg + (size_t)warp * D_))[lane] = o;
    }

    if (STATS) {
        float s = o.x + o.y + o.z + o.w;
        float q = o.x * o.x + o.y * o.y + o.z * o.z + o.w * o.w;
#pragma unroll
        for (int of = 16; of > 0; of >>= 1) {
            s += __shfl_xor_sync(0xffffffffu, s, of);
            q += __shfl_xor_sync(0xffffffffu, q, of);
        }
        if (lane == 0) { ssum[wid] = s; ssq[wid] = q; }
        __syncthreads();
        if (tid == 0) {
            double S = 0.0, Q = 0.0;
#pragma unroll
            for (int i = 0; i < 8; i++) { S += (double)ssum[i]; Q += (double)ssq[i]; }
            atomicAdd(&g_lnred[slot * 2 + 0], S);
            atomicAdd(&g_lnred[slot * 2 + 1], Q);
        }
    }
}

// -------------------- BatchNorm --------------------
__global__ void bnstats_kernel(const float* __restrict__ out) {
    int c = threadIdx.x;
    float s = 0.f, q = 0.f;
    for (int r = blockIdx.x; r < N_; r += gridDim.x) {
        float v = out[(size_t)r * D_ + c];
        s += v; q += v * v;
    }
    atomicAdd(&g_bnsum[c], s);
    atomicAdd(&g_bnsq[c], q);
}

__global__ void bnnorm_kernel(float* __restrict__ out,
                              const float* __restrict__ bng,
                              const float* __restrict__ bnb) {
    int i = blockIdx.x * blockDim.x + threadIdx.x;
    if (i >= N_ * 32) return;
    int c4 = i & 31;
    float4 v  = ((float4*)out)[i];
    float4 su = ((const float4*)g_bnsum)[c4];
    float4 qu = ((const float4*)g_bnsq)[c4];
    float4 g  = ((const float4*)bng)[c4];
    float4 b  = ((const float4*)bnb)[c4];
    const float invN = 1.f / (float)N_;
    float mu, var;
    mu = su.x * invN; var = qu.x * invN - mu * mu;
    v.x = (v.x - mu) * rsqrtf(var + EPS_) * g.x + b.x;
    mu = su.y * invN; var = qu.y * invN - mu * mu;
    v.y = (v.y - mu) * rsqrtf(var + EPS_) * g.y + b.y;
    mu = su.z * invN; var = qu.z * invN - mu * mu;
    v.z = (v.z - mu) * rsqrtf(var + EPS_) * g.z + b.z;
    mu = su.w * invN; var = qu.w * invN - mu * mu;
    v.w = (v.w - mu) * rsqrtf(var + EPS_) * g.w + b.w;
    ((float4*)out)[i] = v;
}

// -------------------- launch --------------------
extern "C" void kernel_launch(void* const* d_in, const int* in_sizes, int n_in,
                              void* d_out, int out_size) {
    const int*   x    = (const int*)d_in[0];
    const int*   ei   = (const int*)d_in[1];
    const float* emb  = (const float*)d_in[2];
    const float* Wl   = (const float*)d_in[3];
    const float* bl   = (const float*)d_in[4];
    const float* Wr   = (const float*)d_in[5];
    const float* br   = (const float*)d_in[6];
    const float* att  = (const float*)d_in[7];
    const float* cb   = (const float*)d_in[8];
    const float* lng  = (const float*)d_in[9];
    const float* lnb  = (const float*)d_in[10];
    const float* linW = (const float*)d_in[11];
    const float* linb = (const float*)d_in[12];
    const float* bng  = (const float*)d_in[13];
    const float* bnb  = (const float*)d_in[14];
    float* out = (float*)d_out;

    float *p_h, *p_xg, *p_xl, *p_xr;
    uint32_t *p_Wph, *p_Wpl;
    cudaGetSymbolAddress((void**)&p_h,  g_h);
    cudaGetSymbolAddress((void**)&p_xg, g_xg);
    cudaGetSymbolAddress((void**)&p_xl, g_xl);
    cudaGetSymbolAddress((void**)&p_xr, g_xr);
    cudaGetSymbolAddress((void**)&p_Wph, g_Wph);
    cudaGetSymbolAddress((void**)&p_Wpl, g_Wpl);

    const int TPB = 256;
    const int GEMM_GRID = (N_ + 31) / 32;            // 938
    const int AGG_GRID  = (N_ * 32 + TPB - 1) / TPB; // warp per node

    // Reordered: gemm0 at launch index 3 (profiler window), CSR build after it.
    zero_kernel<<<(N_ + TPB - 1) / TPB, TPB>>>();                       // 0
    gather_kernel<<<(N_ * 32 + TPB - 1) / TPB, TPB>>>(x, emb);          // 1
    pack_kernel<<<(13 * 8192 + 255) / 256, 256>>>(Wl, Wr, linW);        // 2
    gat_gemm<0,2><<<GEMM_GRID, 256, GSMEM>>>(                           // 3 <- profile me
        p_h, nullptr,
        p_Wph + 0, p_Wpl + 0, p_Wph + (size_t)6 * 8192, p_Wpl + (size_t)6 * 8192,
        bl, br, p_xl, p_xr, nullptr, nullptr, 0);
    hist_kernel<<<(E2_ + TPB - 1) / TPB, TPB>>>(ei);                    // 4
    scan1_kernel<<<30, 1024>>>();                                       // 5
    scan2_kernel<<<1, 32>>>();                                          // 6
    scan3_kernel<<<30, 1024>>>();                                       // 7
    scatter_kernel<<<(E2_ + TPB - 1) / TPB, TPB>>>(ei);                 // 8

    for (int i = 0; i < L_; i++) {
        if (i > 0) {
            const uint32_t* WhL = p_Wph + (size_t)i * 8192;
            const uint32_t* WlL = p_Wpl + (size_t)i * 8192;
            const uint32_t* WhR = p_Wph + (size_t)(6 + i) * 8192;
            const uint32_t* WlR = p_Wpl + (size_t)(6 + i) * 8192;
            gat_gemm<1,2><<<GEMM_GRID, 256, GSMEM>>>(
                p_xg, nullptr, WhL, WlL, WhR, WlR, bl + i * D_, br + i * D_,
                p_xl, p_xr, lng + (i - 1) * D_, lnb + (i - 1) * D_, i - 1);
        }
        if (i < L_ - 1)
            agg_kernel<1><<<AGG_GRID, 256>>>(att + i * D_, cb + i * D_, i);
        else
            agg_kernel<0><<<AGG_GRID, 256>>>(att + i * D_, cb + i * D_, 0);
    }

    gat_gemm<2,1><<<GEMM_GRID, 256, GSMEM>>>(
        p_xg, p_h, p_Wph + (size_t)12 * 8192, p_Wpl + (size_t)12 * 8192,
        nullptr, nullptr, linb, nullptr,
        out, nullptr, nullptr, nullptr, 0);
    bnstats_kernel<<<256, D_>>>(out);
    bnnorm_kernel<<<(N_ * 32 + TPB - 1) / TPB, TPB>>>(out, bng, bnb);
}